// round 17
// baseline (speedup 1.0000x reference)
#include <cuda_runtime.h>
#include <cuda_bf16.h>
#include <cstdint>

// B=4, C=64, H=W=64, PS=4, PD=1, UFSTRIDE=2, STRIDE=1, SCALE=10
// T[u,v,ys,xs] = sum_c bn[c,u,v]*f[c,ys,xs]  (bf16 3-split GEMM, K=192)
// cos[ly,lx,y,x] = sum_{dy,dx} T[cl(2ly+dy-1), cl(2lx+dx-1), cl(y+dy-1), cl(x+dx-1)]
// stage1 (dx) fused in GEMM epilogue; stage2 (dy) 2-ly blocks; 9-tap fuse pass
// computes exp ONCE + block-partial atomic sums; write pass is a pure scale.

#define NB    4
#define NC    64
#define LL    1024
#define PP    3969
#define CSTR  3972
#define SPA   4096
#define GKS   192
#define ROWB  384

#define BM    128
#define BN    128
#define NCHUNK 3
#define ABYTES (BM * 128)
#define BBYTES (BN * 128)
#define BUFBYTES (ABYTES + BBYTES)    // 32768
#define NSTAGE 2
#define PANES_BYTES (4 * 64 * 66 * 4) // 67584
#define SM_BYTES PANES_BYTES
#define S2_SMEM (6 * 4032 * 4)        // 96768

static __device__ float d_invn[NB * NC];
static __device__ __align__(16) __nv_bfloat16 d_A2[(size_t)NB * SPA * GKS];
static __device__ __align__(16) __nv_bfloat16 d_F2[(size_t)NB * SPA * GKS];
static __device__ float d_V  [(size_t)NB * 64 * 32 * 64 * 63];
static __device__ float d_cos [(size_t)NB * LL * CSTR];   // raw fused-input cos
static __device__ float d_tmp [(size_t)NB * LL * CSTR];   // exp(10*cosF*mm)
static __device__ float d_mmk [NB * LL];
static __device__ float d_mmp [NB * PP];
static __device__ float d_sum [NB * PP];
static __device__ float d_rcps[NB * PP];

__device__ __forceinline__ int clamp64(int v) { return min(max(v, 0), 63); }

__device__ __forceinline__ uint32_t smem_u32(const void* p) {
    uint32_t a;
    asm("{ .reg .u64 t; cvta.to.shared.u64 t, %1; cvt.u32.u64 %0, t; }" : "=r"(a) : "l"(p));
    return a;
}
__device__ __forceinline__ void cp_async16(uint32_t dst, const void* src) {
    asm volatile("cp.async.cg.shared.global [%0], [%1], 16;" :: "r"(dst), "l"(src) : "memory");
}
__device__ __forceinline__ void ldsm_x4(uint32_t* r, uint32_t addr) {
    asm volatile("ldmatrix.sync.aligned.m8n8.x4.shared.b16 {%0,%1,%2,%3}, [%4];"
                 : "=r"(r[0]), "=r"(r[1]), "=r"(r[2]), "=r"(r[3]) : "r"(addr));
}
__device__ __forceinline__ void mma_bf16(float* c, const uint32_t* a, const uint32_t* b) {
    asm volatile(
        "mma.sync.aligned.m16n8k16.row.col.f32.bf16.bf16.f32 "
        "{%0,%1,%2,%3}, {%4,%5,%6,%7}, {%8,%9}, {%0,%1,%2,%3};"
        : "+f"(c[0]), "+f"(c[1]), "+f"(c[2]), "+f"(c[3])
        : "r"(a[0]), "r"(a[1]), "r"(a[2]), "r"(a[3]), "r"(b[0]), "r"(b[1]));
}
__device__ __forceinline__ uint32_t swz(uint32_t base, int r, int c) {
    return base + r * 128 + ((c ^ (r & 7)) << 4);
}

// ---------------------------------------------------------------------------
__global__ void norm_kernel(const float* __restrict__ bsrc) {
    int bc = blockIdx.x;
    const float* src = bsrc + (size_t)bc * 4096;
    float s = 0.f;
    for (int i = threadIdx.x; i < 4096; i += 256) {
        float v = src[i];
        s += v * v;
    }
    __shared__ float sh[256];
    sh[threadIdx.x] = s;
    __syncthreads();
    for (int o = 128; o > 0; o >>= 1) {
        if (threadIdx.x < o) sh[threadIdx.x] += sh[threadIdx.x + o];
        __syncthreads();
    }
    if (threadIdx.x == 0) d_invn[bc] = 1.0f / sqrtf(sh[0] + 1e-8f);
}

// ---------------------------------------------------------------------------
__global__ void build_AF_split(const float* __restrict__ bsrc,
                               const float* __restrict__ fsrc) {
    int idx = blockIdx.x * 256 + threadIdx.x;
    int c = idx & 63;
    int s = (idx >> 6) & 4095;
    int b = idx >> 18;
    size_t row = ((size_t)b * SPA + s) * GKS;

    float a = bsrc[((size_t)(b * NC + c)) * 4096 + s] * d_invn[b * NC + c];
    __nv_bfloat16 ahi = __float2bfloat16(a);
    __nv_bfloat16 alo = __float2bfloat16(a - __bfloat162float(ahi));
    d_A2[row + c]       = ahi;
    d_A2[row + 64 + c]  = ahi;
    d_A2[row + 128 + c] = alo;

    float v = fsrc[((size_t)(b * NC + c)) * 4096 + s];
    __nv_bfloat16 fhi = __float2bfloat16(v);
    __nv_bfloat16 flo = __float2bfloat16(v - __bfloat162float(fhi));
    d_F2[row + c]       = fhi;
    d_F2[row + 64 + c]  = flo;
    d_F2[row + 128 + c] = fhi;
}

// ---------------------------------------------------------------------------
__global__ void masks_kernel(const float* __restrict__ mask) {
    int p = blockIdx.x * 256 + threadIdx.x;
    int b = blockIdx.y;
    const float* m = mask + (size_t)b * 4096;
    if (p < PP) {
        int y = p / 63, x = p - 63 * y;
        float s = 0.f;
        #pragma unroll
        for (int i = 0; i < 4; i++)
            #pragma unroll
            for (int j = 0; j < 4; j++)
                s += 1.0f - m[clamp64(y + i - 1) * 64 + clamp64(x + j - 1)];
        d_mmp[b * PP + p] = s * 0.0625f;
    }
    if (p < LL) {
        int ly = p >> 5, lx = p & 31;
        float s = 0.f;
        #pragma unroll
        for (int i = 0; i < 4; i++)
            #pragma unroll
            for (int j = 0; j < 4; j++)
                s += 1.0f - m[clamp64(2 * ly + i - 1) * 64 + clamp64(2 * lx + j - 1)];
        d_mmk[b * LL + p] = s * 0.0625f;
    }
}

// ---------------------------------------------------------------------------
__global__ void zero_sum_kernel() {
    int i = blockIdx.x * 256 + threadIdx.x;
    if (i < NB * PP) d_sum[i] = 0.f;
}

// ---------------------------------------------------------------------------
// bf16 3-split GEMM + fused dx-stencil epilogue -> V  (2 CTAs/SM)
// ---------------------------------------------------------------------------
__global__ void __launch_bounds__(256, 2)
gemm_V_kernel() {
    extern __shared__ char smem[];
    const uint32_t sb = smem_u32(smem);
    const int tid  = threadIdx.x;
    const int wid  = tid >> 5;
    const int lane = tid & 31;
    const int wm   = wid >> 2;
    const int wn   = wid & 3;
    const int bI = blockIdx.z;
    const int m0 = blockIdx.y * BM;
    const int n0 = blockIdx.x * BN;

    const char* Ag = (const char*)d_A2 + ((size_t)bI * SPA + m0) * ROWB;
    const char* Bg = (const char*)d_F2 + ((size_t)bI * SPA + n0) * ROWB;

    float acc[4][4][4];
    #pragma unroll
    for (int mt = 0; mt < 4; mt++)
        #pragma unroll
        for (int nt = 0; nt < 4; nt++)
            #pragma unroll
            for (int e = 0; e < 4; e++) acc[mt][nt][e] = 0.f;

    const int ar = wm * 64 + (lane & 15);
    const int ac = (lane >> 4);
    const int br = wn * 32 + (lane & 7) + ((lane >> 4) << 3);
    const int bc = (lane >> 3) & 1;

    auto load_chunk = [&](int ch, int buf) {
        const uint32_t ab = sb + buf * BUFBYTES;
        const uint32_t bb = ab + ABYTES;
        const size_t koff = (size_t)ch * 128;
        #pragma unroll
        for (int i = 0; i < 4; i++) {
            int idx = i * 256 + tid;
            int r = idx >> 3, c = idx & 7;
            cp_async16(swz(ab, r, c), Ag + (size_t)r * ROWB + koff + c * 16);
        }
        #pragma unroll
        for (int i = 0; i < 4; i++) {
            int idx = i * 256 + tid;
            int r = idx >> 3, c = idx & 7;
            cp_async16(swz(bb, r, c), Bg + (size_t)r * ROWB + koff + c * 16);
        }
        asm volatile("cp.async.commit_group;" ::: "memory");
    };

    load_chunk(0, 0);
    load_chunk(1, 1);

    int buf = 0;
    for (int ch = 0; ch < NCHUNK; ch++) {
        if (ch < NCHUNK - 1) asm volatile("cp.async.wait_group 1;" ::: "memory");
        else                 asm volatile("cp.async.wait_group 0;" ::: "memory");
        __syncthreads();

        const uint32_t ab = sb + buf * BUFBYTES;
        const uint32_t bb = ab + ABYTES;
        #pragma unroll
        for (int ks = 0; ks < 4; ks++) {
            uint32_t afr[4][4];
            #pragma unroll
            for (int mt = 0; mt < 4; mt++)
                ldsm_x4(afr[mt], swz(ab, ar + mt * 16, ks * 2 + ac));
            uint32_t bfr[4][2];
            #pragma unroll
            for (int pp = 0; pp < 2; pp++) {
                uint32_t t[4];
                ldsm_x4(t, swz(bb, br + pp * 16, ks * 2 + bc));
                bfr[2 * pp][0] = t[0]; bfr[2 * pp][1] = t[1];
                bfr[2 * pp + 1][0] = t[2]; bfr[2 * pp + 1][1] = t[3];
            }
            #pragma unroll
            for (int mt = 0; mt < 4; mt++)
                #pragma unroll
                for (int nt = 0; nt < 4; nt++)
                    mma_bf16(acc[mt][nt], afr[mt], bfr[nt]);
        }
        __syncthreads();
        if (ch + NSTAGE < NCHUNK) load_chunk(ch + NSTAGE, buf);
        buf ^= 1;
    }
    __syncthreads();

    // fused stage1 epilogue: pane shared by warp pairs
    float* W = (float*)smem + (wm * 2 + (wn >> 1)) * (64 * 66);
    const int xsh = (wn & 1) * 32;
    #pragma unroll
    for (int mt = 0; mt < 4; mt++) {
        int v0 = mt * 16 + (lane >> 2);
        #pragma unroll
        for (int nt = 0; nt < 4; nt++) {
            int xs = xsh + nt * 8 + 2 * (lane & 3);
            *(float2*)&W[v0 * 66 + xs]       = make_float2(acc[mt][nt][0], acc[mt][nt][1]);
            *(float2*)&W[(v0 + 8) * 66 + xs] = make_float2(acc[mt][nt][2], acc[mt][nt][3]);
        }
    }
    __syncthreads();

    const int u  = (m0 >> 6) + wm;
    const int ys = (n0 >> 6) + (wn >> 1);
    float* Vout = d_V + (((size_t)(bI * 64 + u) * 32) * 64 + ys) * 63;
    const int lx0 = (wn & 1) * 16;
    const int xA = lane;
    const int xB = lane + 32;
    #pragma unroll 4
    for (int li = 0; li < 16; li++) {
        int lx = lx0 + li;
        const float* r0 = W + clamp64(2 * lx - 1) * 66;
        const float* r1 = W + (2 * lx) * 66;
        const float* r2 = W + (2 * lx + 1) * 66;
        const float* r3 = W + clamp64(2 * lx + 2) * 66;
        float* vrow = Vout + (size_t)lx * 4032;
        vrow[xA] = r0[max(xA - 1, 0)] + r1[xA] + r2[xA + 1] + r3[min(xA + 2, 63)];
        if (lane < 31)
            vrow[xB] = r0[xB - 1] + r1[xB] + r2[xB + 1] + r3[min(xB + 2, 63)];
    }
}

// ---------------------------------------------------------------------------
// stage2: 2 ly per block, 6 shared planes. cos[ly*32+lx][y*63+x] = sum_dy ...
// ---------------------------------------------------------------------------
__global__ void stage2_kernel() {
    extern __shared__ float pl[];          // [6][4032]
    int lx = blockIdx.x, t = blockIdx.y, b = blockIdx.z;
    int tid = threadIdx.x;
    #pragma unroll
    for (int i = 0; i < 6; i++) {
        int u = clamp64(4 * t - 1 + i);
        const float* Vp = d_V + (((size_t)(b * 64 + u) * 32 + lx) * 64) * 63;
        for (int idx = tid; idx < 4032; idx += 256)
            pl[i * 4032 + idx] = Vp[idx];
    }
    __syncthreads();
    #pragma unroll
    for (int sub = 0; sub < 2; sub++) {
        int ly = 2 * t + sub;
        float* Crow = d_cos + ((size_t)(b * LL + ly * 32 + lx)) * CSTR;
        for (int o = tid; o < 63 * 63; o += 256) {
            int y = o / 63, x = o - y * 63;
            float s = 0.f;
            #pragma unroll
            for (int dy = 0; dy < 4; dy++)
                s += pl[(2 * sub + dy) * 4032 + clamp64(y + dy - 1) * 63 + x];
            Crow[o] = s;
        }
    }
}

// ---------------------------------------------------------------------------
// fused 9-tap pass + mask + exp (ONCE) + block-partial softmax sums
// grid (125, 16, NB); block 256 = 32 q-lanes x 8 r-threads; 8 r per thread
// ---------------------------------------------------------------------------
__global__ void fused_pass_kernel() {
    int ql = threadIdx.x & 31;
    int rt = threadIdx.x >> 5;
    int q  = blockIdx.x * 32 + ql;
    int rg = blockIdx.y;
    int b  = blockIdx.z;
    bool qv = q < PP;
    int y = q / 63, x = q - 63 * y;
    const float* cb = d_cos + (size_t)b * LL * CSTR;
    float mp = qv ? d_mmp[b * PP + q] : 0.f;
    float psum = 0.f;
    #pragma unroll 2
    for (int i = 0; i < 8; i++) {
        int r = rg * 64 + i * 8 + rt;
        if (!qv) continue;
        int ly = r >> 5, lx = r & 31;
        float s = 0.f;
        #pragma unroll
        for (int d2 = -1; d2 <= 1; d2++) {
            bool vR; int rf;
            int lyd = ly + d2;
            if (lyd >= 0 && lyd < 32) { vR = true;      rf = r + 32 * d2; }
            else if (lyd < 0)         { vR = (lx > 0);  rf = 992 + lx - 1; }
            else                      { vR = (lx < 31); rf = lx + 1; }
            bool vC; int cf;
            int yd = y + d2;
            if (yd >= 0 && yd < 63) { vC = true;      cf = q + 63 * d2; }
            else if (yd < 0)        { vC = (x > 0);   cf = 3906 + x - 1; }
            else                    { vC = (x < 62);  cf = x + 1; }
            if (vR && vC) {
                s += cb[(size_t)rf * CSTR + cf];
                if (rf > 0 && cf > 0)         s += cb[(size_t)(rf - 1) * CSTR + cf - 1];
                if (rf < 1023 && cf < PP - 1) s += cb[(size_t)(rf + 1) * CSTR + cf + 1];
            }
        }
        float mk = d_mmk[b * LL + r];
        float mm = ((mk > mp && mp > 0.5f) || (mk == 1.0f)) ? 1.0f : 0.0f;
        float e = __expf(10.0f * s * mm);
        d_tmp[((size_t)(b * LL + r)) * CSTR + q] = e;
        psum += e;
    }
    __shared__ float sh[8][33];
    sh[rt][ql] = psum;
    __syncthreads();
    if (rt == 0 && qv) {
        float S = 0.f;
        #pragma unroll
        for (int t = 0; t < 8; t++) S += sh[t][ql];
        atomicAdd(&d_sum[b * PP + q], S);
    }
}

// ---------------------------------------------------------------------------
__global__ void rcp_kernel() {
    int i = blockIdx.x * 256 + threadIdx.x;
    if (i < NB * PP) d_rcps[i] = 1.0f / d_sum[i];
}

// ---------------------------------------------------------------------------
__global__ void smax_write_kernel(float* __restrict__ out) {
    int q = blockIdx.x * 256 + threadIdx.x;
    if (q >= PP) return;
    int bl = blockIdx.y;
    int b = bl >> 10;
    out[(size_t)bl * PP + q] = d_tmp[(size_t)bl * CSTR + q] * d_rcps[b * PP + q];
}

// ---------------------------------------------------------------------------
extern "C" void kernel_launch(void* const* d_in, const int* in_sizes, int n_in,
                              void* d_out, int out_size) {
    const float* f    = (const float*)d_in[0];
    const float* bsrc = (const float*)d_in[1];
    const float* mask = (const float*)d_in[2];
    float* out = (float*)d_out;

    cudaFuncSetAttribute(gemm_V_kernel,
                         cudaFuncAttributeMaxDynamicSharedMemorySize, SM_BYTES);
    cudaFuncSetAttribute(stage2_kernel,
                         cudaFuncAttributeMaxDynamicSharedMemorySize, S2_SMEM);

    norm_kernel<<<NB * NC, 256>>>(bsrc);
    build_AF_split<<<(NB * SPA * NC) / 256, 256>>>(bsrc, f);
    masks_kernel<<<dim3((PP + 255) / 256, NB), 256>>>(mask);
    zero_sum_kernel<<<(NB * PP + 255) / 256, 256>>>();

    gemm_V_kernel<<<dim3(SPA / BN, SPA / BM, NB), 256, SM_BYTES>>>();

    stage2_kernel<<<dim3(32, 16, NB), 256, S2_SMEM>>>();

    fused_pass_kernel<<<dim3(125, 16, NB), 256>>>();
    rcp_kernel<<<(NB * PP + 255) / 256, 256>>>();

    smax_write_kernel<<<dim3((PP + 255) / 256, NB * LL), 256>>>(out);
}